// round 13
// baseline (speedup 1.0000x reference)
#include <cuda_runtime.h>
#include <math.h>
#include <stdint.h>

#define NN 100000
#define EE 1600000
#define DHID 256
#define DOUT 40
#define NB_SCAN ((NN + 1023) / 1024)

// ---------------- scratch (device globals; zero-initialized at module load) ----------------
__device__ int   g_outdeg[NN];
__device__ int   g_indeg[NN];
__device__ float g_isout[NN];
__device__ float g_isin[NN];
__device__ int   g_rowptr[NN + 1];
__device__ int   g_fill[NN];
__device__ int   g_bsum[NB_SCAN + 1];
__device__ int   g_cols[EE];
__device__ float g_z[(size_t)NN * DHID];   // GEMM output
__device__ float g_h[(size_t)NN * DHID];   // SpMM output, PRE-SCALED by isout

// Counters (g_outdeg/g_indeg/g_fill) are zeroed AFTER their last use each
// replay (scan_final / spmm), so every replay starts clean.

// ---------------- graph prep ----------------
__global__ void degree_kernel(const int* __restrict__ src, const int* __restrict__ dst) {
    int e = blockIdx.x * blockDim.x + threadIdx.x;
    if (e < EE) {
        atomicAdd(&g_outdeg[src[e]], 1);
        atomicAdd(&g_indeg[dst[e]], 1);
    }
}

__global__ void scan_partial_kernel() {
    __shared__ int ws[32];
    const int b = blockIdx.x, tid = threadIdx.x;
    const int i = b * 1024 + tid;
    int x = (i < NN) ? g_indeg[i] : 0;
    #pragma unroll
    for (int off = 16; off > 0; off >>= 1) x += __shfl_down_sync(0xffffffffu, x, off);
    if ((tid & 31) == 0) ws[tid >> 5] = x;
    __syncthreads();
    if (tid < 32) {
        int w = ws[tid];
        #pragma unroll
        for (int off = 16; off > 0; off >>= 1) w += __shfl_down_sync(0xffffffffu, w, off);
        if (tid == 0) g_bsum[b] = w;
    }
}

__global__ void scan_mid_kernel() {
    if (threadIdx.x == 0) {
        int run = 0;
        for (int b = 0; b < NB_SCAN; b++) { int t = g_bsum[b]; g_bsum[b] = run; run += t; }
        g_rowptr[NN] = run;
    }
}

// rowptr + isout/isin, then zero degree counters for the next replay
__global__ void scan_final_kernel() {
    __shared__ int ws[32];
    const int b = blockIdx.x, tid = threadIdx.x;
    const int lane = tid & 31, wid = tid >> 5;
    const int i = b * 1024 + tid;
    const int v = (i < NN) ? g_indeg[i] : 0;
    int x = v;
    #pragma unroll
    for (int off = 1; off < 32; off <<= 1) {
        int y = __shfl_up_sync(0xffffffffu, x, off);
        if (lane >= off) x += y;
    }
    if (lane == 31) ws[wid] = x;
    __syncthreads();
    if (wid == 0) {
        int w = ws[lane];
        #pragma unroll
        for (int off = 1; off < 32; off <<= 1) {
            int y = __shfl_up_sync(0xffffffffu, w, off);
            if (lane >= off) w += y;
        }
        ws[lane] = w;
    }
    __syncthreads();
    int incl = x + ((wid > 0) ? ws[wid - 1] : 0);
    if (i < NN) {
        g_rowptr[i] = g_bsum[b] + incl - v;
        int od = g_outdeg[i];
        g_isout[i] = (od > 0) ? rsqrtf((float)od) : 0.f;
        g_isin[i]  = (v > 0) ? rsqrtf((float)v) : 0.f;
        g_indeg[i]  = 0;
        g_outdeg[i] = 0;
    }
}

__global__ void csr_fill_kernel(const int* __restrict__ src, const int* __restrict__ dst) {
    int e = blockIdx.x * blockDim.x + threadIdx.x;
    if (e < EE) {
        int d = dst[e];
        int p = g_rowptr[d] + atomicAdd(&g_fill[d], 1);
        g_cols[p] = src[e];
    }
}

// ---------------- GEMM: g_z[r,c] = sum_k A[r,k] * W[k,c]  (NO row scaling) ----------------
#define FMA2(d, a, b) asm("fma.rn.f32x2 %0, %1, %2, %0;" : "+l"(d) : "l"(a), "l"(b))

__global__ __launch_bounds__(256, 2)
void gemm_kernel(const float* __restrict__ Xin, int use_x,
                 const float* __restrict__ W, int nrows, int ncols)
{
    const float* __restrict__ A = use_x ? Xin : (const float*)g_h;
    __shared__ float As[16][128];                 // [k][m]
    __shared__ unsigned long long BdS[16][128];   // [k][swizzled pair slot]

    const int tid = threadIdx.x;
    const int tx = tid & 15, ty = tid >> 4;
    const int rowBase = blockIdx.y * 128;
    const int colBase = blockIdx.x * 128;

    const int lr = tid >> 1;
    const int lk = (tid & 1) * 8;
    const int arow = rowBase + lr;

    const int bk  = tid >> 4;
    const int btx = tid & 15;
    const int bc0 = colBase + btx * 8;

    unsigned long long acc[4][8];
    #pragma unroll
    for (int i = 0; i < 4; i++)
        #pragma unroll
        for (int j = 0; j < 8; j++) acc[i][j] = 0ull;

    for (int k0 = 0; k0 < 256; k0 += 16) {
        float4 a0 = make_float4(0.f, 0.f, 0.f, 0.f), a1 = a0;
        if (arow < nrows) {
            const float4* Ar = reinterpret_cast<const float4*>(A + (size_t)arow * 256);
            a0 = Ar[(k0 + lk) >> 2];
            a1 = Ar[(k0 + lk + 4) >> 2];
        }
        As[lk + 0][lr] = a0.x; As[lk + 1][lr] = a0.y;
        As[lk + 2][lr] = a0.z; As[lk + 3][lr] = a0.w;
        As[lk + 4][lr] = a1.x; As[lk + 5][lr] = a1.y;
        As[lk + 6][lr] = a1.z; As[lk + 7][lr] = a1.w;

        float bv[8];
        {
            const float* Wr = &W[(size_t)(k0 + bk) * ncols + bc0];
            float4 w0 = *reinterpret_cast<const float4*>(Wr);
            float4 w1 = *reinterpret_cast<const float4*>(Wr + 4);
            bv[0] = w0.x; bv[1] = w0.y; bv[2] = w0.z; bv[3] = w0.w;
            bv[4] = w1.x; bv[5] = w1.y; bv[6] = w1.z; bv[7] = w1.w;
        }
        #pragma unroll
        for (int m = 0; m < 8; m++) {
            unsigned int b = __float_as_uint(bv[m]);
            unsigned long long pv = ((unsigned long long)b << 32) | (unsigned long long)b;
            BdS[bk][m * 16 + btx] = pv;
        }
        __syncthreads();

        #pragma unroll
        for (int kk = 0; kk < 16; kk++) {
            unsigned long long a2[4], bd[8];
            #pragma unroll
            for (int i = 0; i < 4; i++)
                a2[i] = *reinterpret_cast<const unsigned long long*>(&As[kk][ty * 8 + 2 * i]);
            #pragma unroll
            for (int j = 0; j < 8; j++)
                bd[j] = BdS[kk][j * 16 + tx];
            #pragma unroll
            for (int i = 0; i < 4; i++)
                #pragma unroll
                for (int j = 0; j < 8; j++)
                    FMA2(acc[i][j], a2[i], bd[j]);
        }
        __syncthreads();
    }

    const int c0 = colBase + tx * 8;
    #pragma unroll
    for (int i = 0; i < 4; i++) {
        #pragma unroll
        for (int h = 0; h < 2; h++) {
            int r = rowBase + ty * 8 + 2 * i + h;
            if (r >= nrows) continue;
            float vals[8];
            #pragma unroll
            for (int j = 0; j < 8; j++) {
                unsigned long long p = acc[i][j];
                unsigned int bits = h ? (unsigned int)(p >> 32) : (unsigned int)p;
                vals[j] = __uint_as_float(bits);
            }
            float* zr = &g_z[(size_t)r * ncols + c0];
            *reinterpret_cast<float4*>(zr)     = make_float4(vals[0], vals[1], vals[2], vals[3]);
            *reinterpret_cast<float4*>(zr + 4) = make_float4(vals[4], vals[5], vals[6], vals[7]);
        }
    }
}

// ---------------- narrow GEMM for layer 3: ncols=40, BN=64 tile, 128 threads ----------------
__global__ __launch_bounds__(128, 4)
void gemm64_kernel(const float* __restrict__ W, int nrows, int ncols)
{
    const float* __restrict__ A = (const float*)g_h;
    __shared__ float As[16][128];
    __shared__ unsigned long long BdS[16][64];

    const int tid = threadIdx.x;
    const int tx = tid & 7, ty = tid >> 3;
    const int rowBase = blockIdx.x * 128;

    const int lr = tid;
    const int arow = rowBase + lr;

    const int bk  = tid >> 3;
    const int btx = tid & 7;
    const int bc0 = btx * 8;

    unsigned long long acc[4][8];
    #pragma unroll
    for (int i = 0; i < 4; i++)
        #pragma unroll
        for (int j = 0; j < 8; j++) acc[i][j] = 0ull;

    for (int k0 = 0; k0 < 256; k0 += 16) {
        if (arow < nrows) {
            const float4* Ar = reinterpret_cast<const float4*>(A + (size_t)arow * 256);
            #pragma unroll
            for (int q = 0; q < 4; q++) {
                float4 a = Ar[(k0 >> 2) + q];
                As[q * 4 + 0][lr] = a.x;
                As[q * 4 + 1][lr] = a.y;
                As[q * 4 + 2][lr] = a.z;
                As[q * 4 + 3][lr] = a.w;
            }
        } else {
            #pragma unroll
            for (int q = 0; q < 16; q++) As[q][lr] = 0.f;
        }
        float bv[8];
        #pragma unroll
        for (int m = 0; m < 8; m++)
            bv[m] = (bc0 + m < ncols) ? W[(size_t)(k0 + bk) * ncols + bc0 + m] : 0.f;
        #pragma unroll
        for (int m = 0; m < 8; m++) {
            unsigned int b = __float_as_uint(bv[m]);
            BdS[bk][m * 8 + btx] = ((unsigned long long)b << 32) | (unsigned long long)b;
        }
        __syncthreads();

        #pragma unroll
        for (int kk = 0; kk < 16; kk++) {
            unsigned long long a2[4], bd[8];
            #pragma unroll
            for (int i = 0; i < 4; i++)
                a2[i] = *reinterpret_cast<const unsigned long long*>(&As[kk][ty * 8 + 2 * i]);
            #pragma unroll
            for (int j = 0; j < 8; j++)
                bd[j] = BdS[kk][j * 8 + tx];
            #pragma unroll
            for (int i = 0; i < 4; i++)
                #pragma unroll
                for (int j = 0; j < 8; j++)
                    FMA2(acc[i][j], a2[i], bd[j]);
        }
        __syncthreads();
    }

    const int c0 = tx * 8;
    #pragma unroll
    for (int i = 0; i < 4; i++) {
        #pragma unroll
        for (int h = 0; h < 2; h++) {
            int r = rowBase + ty * 8 + 2 * i + h;
            if (r >= nrows) continue;
            #pragma unroll
            for (int j = 0; j < 8; j++) {
                if (c0 + j < ncols) {
                    unsigned long long p = acc[i][j];
                    unsigned int bits = h ? (unsigned int)(p >> 32) : (unsigned int)p;
                    g_z[(size_t)r * ncols + c0 + j] = __uint_as_float(bits);
                }
            }
        }
    }
}

// ---------------- SpMM gather, warp-per-node, feature-split, 8-edge unroll ----------------
// g_h[n,d] = relu(isin[n]*sum + b[d]) * isout[n]  (pre-scaled for next GEMM).
// gscale: multiply gathered rows by isout[src] (layer 1 only).
__global__ __launch_bounds__(256)
void spmm_warp_kernel(const float* __restrict__ bias, int half, int gscale)
{
    const int warp = threadIdx.x >> 5;
    const int lane = threadIdx.x & 31;
    const int n = blockIdx.x * 8 + warp;
    if (n >= NN) return;
    const int dbase = half * 128 + lane * 4;

    const int beg = g_rowptr[n];
    const int end = g_rowptr[n + 1];
    if (lane == 0 && half == 0) g_fill[n] = 0;   // reset CSR fill counter for next replay

    float4 acc = make_float4(0.f, 0.f, 0.f, 0.f);
    int p = beg;

    // 8-edge unroll: batch the 8 index loads, then 8 independent LDG.128 gathers.
    for (; p + 8 <= end; p += 8) {
        int s[8];
        #pragma unroll
        for (int q = 0; q < 8; q++) s[q] = __ldg(&g_cols[p + q]);
        float4 v[8];
        #pragma unroll
        for (int q = 0; q < 8; q++)
            v[q] = __ldg((const float4*)(g_z + (size_t)s[q] * 256 + dbase));
        if (gscale) {
            float o[8];
            #pragma unroll
            for (int q = 0; q < 8; q++) o[q] = __ldg(&g_isout[s[q]]);
            #pragma unroll
            for (int q = 0; q < 8; q++) {
                acc.x = fmaf(v[q].x, o[q], acc.x);
                acc.y = fmaf(v[q].y, o[q], acc.y);
                acc.z = fmaf(v[q].z, o[q], acc.z);
                acc.w = fmaf(v[q].w, o[q], acc.w);
            }
        } else {
            acc.x += ((v[0].x + v[1].x) + (v[2].x + v[3].x)) + ((v[4].x + v[5].x) + (v[6].x + v[7].x));
            acc.y += ((v[0].y + v[1].y) + (v[2].y + v[3].y)) + ((v[4].y + v[5].y) + (v[6].y + v[7].y));
            acc.z += ((v[0].z + v[1].z) + (v[2].z + v[3].z)) + ((v[4].z + v[5].z) + (v[6].z + v[7].z));
            acc.w += ((v[0].w + v[1].w) + (v[2].w + v[3].w)) + ((v[4].w + v[5].w) + (v[6].w + v[7].w));
        }
    }
    for (; p < end; ++p) {
        const int s = __ldg(&g_cols[p]);
        const float4 v = __ldg((const float4*)(g_z + (size_t)s * 256 + dbase));
        const float o = gscale ? __ldg(&g_isout[s]) : 1.0f;
        acc.x = fmaf(v.x, o, acc.x); acc.y = fmaf(v.y, o, acc.y);
        acc.z = fmaf(v.z, o, acc.z); acc.w = fmaf(v.w, o, acc.w);
    }

    const float isn = g_isin[n];
    const float osc = g_isout[n];   // pre-scale for next layer's GEMM
    const float4 b4 = *(const float4*)(bias + dbase);
    float4 r;
    r.x = fmaxf(fmaf(acc.x, isn, b4.x), 0.f) * osc;
    r.y = fmaxf(fmaf(acc.y, isn, b4.y), 0.f) * osc;
    r.z = fmaxf(fmaf(acc.z, isn, b4.z), 0.f) * osc;
    r.w = fmaxf(fmaf(acc.w, isn, b4.w), 0.f) * osc;
    *(float4*)(g_h + (size_t)n * 256 + dbase) = r;
}

// ---------------- layer-3 SpMM (D=40) + log_softmax, warp-per-node ----------------
// Lanes 0..19 each own dims (2*lane, 2*lane+1) as a float2; gathers are coalesced
// 160B row reads. Max/sum reductions via full-warp shuffles; no smem, no syncs.
__global__ __launch_bounds__(256)
void spmm_logsoftmax_kernel(const float* __restrict__ bias, float* __restrict__ out)
{
    const int warp = threadIdx.x >> 5;
    const int lane = threadIdx.x & 31;
    const int n = blockIdx.x * 8 + warp;
    if (n >= NN) return;
    const bool act = (lane < DOUT / 2);   // lanes 0..19
    const int d0 = lane * 2;

    const int beg = g_rowptr[n];
    const int end = g_rowptr[n + 1];

    float2 acc = make_float2(0.f, 0.f);
    int p = beg;
    for (; p + 4 <= end; p += 4) {
        int s[4];
        #pragma unroll
        for (int q = 0; q < 4; q++) s[q] = __ldg(&g_cols[p + q]);
        if (act) {
            #pragma unroll
            for (int q = 0; q < 4; q++) {
                const float2 v = __ldg((const float2*)(g_z + (size_t)s[q] * DOUT + d0));
                acc.x += v.x; acc.y += v.y;
            }
        }
    }
    for (; p < end; ++p) {
        const int s = __ldg(&g_cols[p]);
        if (act) {
            const float2 v = __ldg((const float2*)(g_z + (size_t)s * DOUT + d0));
            acc.x += v.x; acc.y += v.y;
        }
    }

    const float isn = g_isin[n];
    float v0 = -INFINITY, v1 = -INFINITY;
    if (act) {
        v0 = fmaf(acc.x, isn, __ldg(&bias[d0]));
        v1 = fmaf(acc.y, isn, __ldg(&bias[d0 + 1]));
    }

    // warp max-reduce
    float mx = fmaxf(v0, v1);
    #pragma unroll
    for (int off = 16; off > 0; off >>= 1)
        mx = fmaxf(mx, __shfl_xor_sync(0xffffffffu, mx, off));

    // warp sum-reduce of exps
    float e = act ? (expf(v0 - mx) + expf(v1 - mx)) : 0.f;
    #pragma unroll
    for (int off = 16; off > 0; off >>= 1)
        e += __shfl_xor_sync(0xffffffffu, e, off);

    const float lse = mx + logf(e);
    if (act) {
        float2 r = make_float2(v0 - lse, v1 - lse);
        *(float2*)(out + (size_t)n * DOUT + d0) = r;
    }
}

// ---------------- launch ----------------
extern "C" void kernel_launch(void* const* d_in, const int* in_sizes, int n_in,
                              void* d_out, int out_size)
{
    const float* x  = (const float*)d_in[0];
    const float* W1 = (const float*)d_in[1];
    const float* b1 = (const float*)d_in[2];
    const float* W2 = (const float*)d_in[3];
    const float* b2 = (const float*)d_in[4];
    const float* W3 = (const float*)d_in[5];
    const float* b3 = (const float*)d_in[6];
    const int*  src = (const int*)d_in[7];
    const int*  dst = (const int*)d_in[8];
    float* out = (float*)d_out;

    // side stream + fork/join events (created once; resources, not work)
    static cudaStream_t s2 = nullptr;
    static cudaEvent_t ev_fork = nullptr, ev_join = nullptr;
    if (s2 == nullptr) {
        cudaStreamCreateWithFlags(&s2, cudaStreamNonBlocking);
        cudaEventCreateWithFlags(&ev_fork, cudaEventDisableTiming);
        cudaEventCreateWithFlags(&ev_join, cudaEventDisableTiming);
    }

    const int nb_e = (EE + 255) / 256;
    const int gm = (NN + 127) / 128;
    const int gw = (NN + 7) / 8;

    // fork: prep chain on s2, GEMM1 (no graph deps) on main stream
    cudaEventRecord(ev_fork, 0);
    cudaStreamWaitEvent(s2, ev_fork, 0);

    degree_kernel<<<nb_e, 256, 0, s2>>>(src, dst);
    scan_partial_kernel<<<NB_SCAN, 1024, 0, s2>>>();
    scan_mid_kernel<<<1, 32, 0, s2>>>();
    scan_final_kernel<<<NB_SCAN, 1024, 0, s2>>>();
    csr_fill_kernel<<<nb_e, 256, 0, s2>>>(src, dst);
    cudaEventRecord(ev_join, s2);

    gemm_kernel<<<dim3(2, gm), 256>>>(x, 1, W1, NN, 256);   // z1 = x @ W1

    // join: SpMM1 needs both z1 and the graph
    cudaStreamWaitEvent(0, ev_join, 0);

    // layer 1: h1 = relu(isin * sum isout[s]*z1[s] + b1) * isout
    spmm_warp_kernel<<<gw, 256>>>(b1, 0, 1);
    spmm_warp_kernel<<<gw, 256>>>(b1, 1, 1);

    // layer 2: z2 = h1 @ W2 ; h2 = relu(isin * sum z2[s] + b2) * isout
    gemm_kernel<<<dim3(2, gm), 256>>>(x, 0, W2, NN, 256);
    spmm_warp_kernel<<<gw, 256>>>(b2, 0, 0);
    spmm_warp_kernel<<<gw, 256>>>(b2, 1, 0);

    // layer 3: z3 = h2 @ W3 ; out = log_softmax(isin * sum z3[s] + b3)
    gemm64_kernel<<<gm, 128>>>(W3, NN, DOUT);
    spmm_logsoftmax_kernel<<<gw, 256>>>(b3, out);
}

// round 14
// speedup vs baseline: 1.0634x; 1.0634x over previous
#include <cuda_runtime.h>
#include <math.h>
#include <stdint.h>

#define NN 100000
#define EE 1600000
#define DHID 256
#define DOUT 40
#define NB_SCAN ((NN + 1023) / 1024)

// ---------------- scratch (device globals; zero-initialized at module load) ----------------
__device__ int   g_outdeg[NN];
__device__ int   g_indeg[NN];
__device__ float g_isout[NN];
__device__ float g_isin[NN];
__device__ int   g_rowptr[NN + 1];
__device__ int   g_fill[NN];
__device__ int   g_bsum[NB_SCAN + 1];
__device__ int   g_cols[EE];
__device__ float g_z[(size_t)NN * DHID];   // GEMM output
__device__ float g_h[(size_t)NN * DHID];   // SpMM output, PRE-SCALED by isout

// Counters (g_outdeg/g_indeg/g_fill) are zeroed AFTER their last use each
// replay (scan_final / spmm), so every replay starts clean.

// ---------------- graph prep ----------------
__global__ void degree_kernel(const int* __restrict__ src, const int* __restrict__ dst) {
    int e = blockIdx.x * blockDim.x + threadIdx.x;
    if (e < EE) {
        atomicAdd(&g_outdeg[src[e]], 1);
        atomicAdd(&g_indeg[dst[e]], 1);
    }
}

__global__ void scan_partial_kernel() {
    __shared__ int ws[32];
    const int b = blockIdx.x, tid = threadIdx.x;
    const int i = b * 1024 + tid;
    int x = (i < NN) ? g_indeg[i] : 0;
    #pragma unroll
    for (int off = 16; off > 0; off >>= 1) x += __shfl_down_sync(0xffffffffu, x, off);
    if ((tid & 31) == 0) ws[tid >> 5] = x;
    __syncthreads();
    if (tid < 32) {
        int w = ws[tid];
        #pragma unroll
        for (int off = 16; off > 0; off >>= 1) w += __shfl_down_sync(0xffffffffu, w, off);
        if (tid == 0) g_bsum[b] = w;
    }
}

__global__ void scan_mid_kernel() {
    if (threadIdx.x == 0) {
        int run = 0;
        for (int b = 0; b < NB_SCAN; b++) { int t = g_bsum[b]; g_bsum[b] = run; run += t; }
        g_rowptr[NN] = run;
    }
}

// rowptr + isout/isin, then zero degree counters for the next replay
__global__ void scan_final_kernel() {
    __shared__ int ws[32];
    const int b = blockIdx.x, tid = threadIdx.x;
    const int lane = tid & 31, wid = tid >> 5;
    const int i = b * 1024 + tid;
    const int v = (i < NN) ? g_indeg[i] : 0;
    int x = v;
    #pragma unroll
    for (int off = 1; off < 32; off <<= 1) {
        int y = __shfl_up_sync(0xffffffffu, x, off);
        if (lane >= off) x += y;
    }
    if (lane == 31) ws[wid] = x;
    __syncthreads();
    if (wid == 0) {
        int w = ws[lane];
        #pragma unroll
        for (int off = 1; off < 32; off <<= 1) {
            int y = __shfl_up_sync(0xffffffffu, w, off);
            if (lane >= off) w += y;
        }
        ws[lane] = w;
    }
    __syncthreads();
    int incl = x + ((wid > 0) ? ws[wid - 1] : 0);
    if (i < NN) {
        g_rowptr[i] = g_bsum[b] + incl - v;
        int od = g_outdeg[i];
        g_isout[i] = (od > 0) ? rsqrtf((float)od) : 0.f;
        g_isin[i]  = (v > 0) ? rsqrtf((float)v) : 0.f;
        g_indeg[i]  = 0;
        g_outdeg[i] = 0;
    }
}

__global__ void csr_fill_kernel(const int* __restrict__ src, const int* __restrict__ dst) {
    int e = blockIdx.x * blockDim.x + threadIdx.x;
    if (e < EE) {
        int d = dst[e];
        int p = g_rowptr[d] + atomicAdd(&g_fill[d], 1);
        g_cols[p] = src[e];
    }
}

// ---------------- GEMM: g_z[r,c] = sum_k A[r,k] * W[k,c]  (NO row scaling) ----------------
#define FMA2(d, a, b) asm("fma.rn.f32x2 %0, %1, %2, %0;" : "+l"(d) : "l"(a), "l"(b))

__global__ __launch_bounds__(256, 2)
void gemm_kernel(const float* __restrict__ Xin, int use_x,
                 const float* __restrict__ W, int nrows, int ncols)
{
    const float* __restrict__ A = use_x ? Xin : (const float*)g_h;
    __shared__ float As[16][128];                 // [k][m]
    __shared__ unsigned long long BdS[16][128];   // [k][swizzled pair slot]

    const int tid = threadIdx.x;
    const int tx = tid & 15, ty = tid >> 4;
    const int rowBase = blockIdx.y * 128;
    const int colBase = blockIdx.x * 128;

    const int lr = tid >> 1;
    const int lk = (tid & 1) * 8;
    const int arow = rowBase + lr;

    const int bk  = tid >> 4;
    const int btx = tid & 15;
    const int bc0 = colBase + btx * 8;

    unsigned long long acc[4][8];
    #pragma unroll
    for (int i = 0; i < 4; i++)
        #pragma unroll
        for (int j = 0; j < 8; j++) acc[i][j] = 0ull;

    for (int k0 = 0; k0 < 256; k0 += 16) {
        float4 a0 = make_float4(0.f, 0.f, 0.f, 0.f), a1 = a0;
        if (arow < nrows) {
            const float4* Ar = reinterpret_cast<const float4*>(A + (size_t)arow * 256);
            a0 = Ar[(k0 + lk) >> 2];
            a1 = Ar[(k0 + lk + 4) >> 2];
        }
        As[lk + 0][lr] = a0.x; As[lk + 1][lr] = a0.y;
        As[lk + 2][lr] = a0.z; As[lk + 3][lr] = a0.w;
        As[lk + 4][lr] = a1.x; As[lk + 5][lr] = a1.y;
        As[lk + 6][lr] = a1.z; As[lk + 7][lr] = a1.w;

        float bv[8];
        {
            const float* Wr = &W[(size_t)(k0 + bk) * ncols + bc0];
            float4 w0 = *reinterpret_cast<const float4*>(Wr);
            float4 w1 = *reinterpret_cast<const float4*>(Wr + 4);
            bv[0] = w0.x; bv[1] = w0.y; bv[2] = w0.z; bv[3] = w0.w;
            bv[4] = w1.x; bv[5] = w1.y; bv[6] = w1.z; bv[7] = w1.w;
        }
        #pragma unroll
        for (int m = 0; m < 8; m++) {
            unsigned int b = __float_as_uint(bv[m]);
            unsigned long long pv = ((unsigned long long)b << 32) | (unsigned long long)b;
            BdS[bk][m * 16 + btx] = pv;
        }
        __syncthreads();

        #pragma unroll
        for (int kk = 0; kk < 16; kk++) {
            unsigned long long a2[4], bd[8];
            #pragma unroll
            for (int i = 0; i < 4; i++)
                a2[i] = *reinterpret_cast<const unsigned long long*>(&As[kk][ty * 8 + 2 * i]);
            #pragma unroll
            for (int j = 0; j < 8; j++)
                bd[j] = BdS[kk][j * 16 + tx];
            #pragma unroll
            for (int i = 0; i < 4; i++)
                #pragma unroll
                for (int j = 0; j < 8; j++)
                    FMA2(acc[i][j], a2[i], bd[j]);
        }
        __syncthreads();
    }

    const int c0 = colBase + tx * 8;
    #pragma unroll
    for (int i = 0; i < 4; i++) {
        #pragma unroll
        for (int h = 0; h < 2; h++) {
            int r = rowBase + ty * 8 + 2 * i + h;
            if (r >= nrows) continue;
            float vals[8];
            #pragma unroll
            for (int j = 0; j < 8; j++) {
                unsigned long long p = acc[i][j];
                unsigned int bits = h ? (unsigned int)(p >> 32) : (unsigned int)p;
                vals[j] = __uint_as_float(bits);
            }
            float* zr = &g_z[(size_t)r * ncols + c0];
            *reinterpret_cast<float4*>(zr)     = make_float4(vals[0], vals[1], vals[2], vals[3]);
            *reinterpret_cast<float4*>(zr + 4) = make_float4(vals[4], vals[5], vals[6], vals[7]);
        }
    }
}

// ---------------- narrow GEMM for layer 3: ncols=40, BN=64 tile, 128 threads ----------------
__global__ __launch_bounds__(128, 4)
void gemm64_kernel(const float* __restrict__ W, int nrows, int ncols)
{
    const float* __restrict__ A = (const float*)g_h;
    __shared__ float As[16][128];
    __shared__ unsigned long long BdS[16][64];

    const int tid = threadIdx.x;
    const int tx = tid & 7, ty = tid >> 3;
    const int rowBase = blockIdx.x * 128;

    const int lr = tid;
    const int arow = rowBase + lr;

    const int bk  = tid >> 3;
    const int btx = tid & 7;
    const int bc0 = btx * 8;

    unsigned long long acc[4][8];
    #pragma unroll
    for (int i = 0; i < 4; i++)
        #pragma unroll
        for (int j = 0; j < 8; j++) acc[i][j] = 0ull;

    for (int k0 = 0; k0 < 256; k0 += 16) {
        if (arow < nrows) {
            const float4* Ar = reinterpret_cast<const float4*>(A + (size_t)arow * 256);
            #pragma unroll
            for (int q = 0; q < 4; q++) {
                float4 a = Ar[(k0 >> 2) + q];
                As[q * 4 + 0][lr] = a.x;
                As[q * 4 + 1][lr] = a.y;
                As[q * 4 + 2][lr] = a.z;
                As[q * 4 + 3][lr] = a.w;
            }
        } else {
            #pragma unroll
            for (int q = 0; q < 16; q++) As[q][lr] = 0.f;
        }
        float bv[8];
        #pragma unroll
        for (int m = 0; m < 8; m++)
            bv[m] = (bc0 + m < ncols) ? W[(size_t)(k0 + bk) * ncols + bc0 + m] : 0.f;
        #pragma unroll
        for (int m = 0; m < 8; m++) {
            unsigned int b = __float_as_uint(bv[m]);
            BdS[bk][m * 8 + btx] = ((unsigned long long)b << 32) | (unsigned long long)b;
        }
        __syncthreads();

        #pragma unroll
        for (int kk = 0; kk < 16; kk++) {
            unsigned long long a2[4], bd[8];
            #pragma unroll
            for (int i = 0; i < 4; i++)
                a2[i] = *reinterpret_cast<const unsigned long long*>(&As[kk][ty * 8 + 2 * i]);
            #pragma unroll
            for (int j = 0; j < 8; j++)
                bd[j] = BdS[kk][j * 8 + tx];
            #pragma unroll
            for (int i = 0; i < 4; i++)
                #pragma unroll
                for (int j = 0; j < 8; j++)
                    FMA2(acc[i][j], a2[i], bd[j]);
        }
        __syncthreads();
    }

    const int c0 = tx * 8;
    #pragma unroll
    for (int i = 0; i < 4; i++) {
        #pragma unroll
        for (int h = 0; h < 2; h++) {
            int r = rowBase + ty * 8 + 2 * i + h;
            if (r >= nrows) continue;
            #pragma unroll
            for (int j = 0; j < 8; j++) {
                if (c0 + j < ncols) {
                    unsigned long long p = acc[i][j];
                    unsigned int bits = h ? (unsigned int)(p >> 32) : (unsigned int)p;
                    g_z[(size_t)r * ncols + c0 + j] = __uint_as_float(bits);
                }
            }
        }
    }
}

// ---------------- SpMM gather, warp-per-node, feature-split, 4-edge unroll ----------------
// g_h[n,d] = relu(isin[n]*sum + b[d]) * isout[n]  (pre-scaled for next GEMM).
// gscale: multiply gathered rows by isout[src] (layer 1 only).
__global__ __launch_bounds__(256)
void spmm_warp_kernel(const float* __restrict__ bias, int half, int gscale)
{
    const int warp = threadIdx.x >> 5;
    const int lane = threadIdx.x & 31;
    const int n = blockIdx.x * 8 + warp;
    if (n >= NN) return;
    const int dbase = half * 128 + lane * 4;

    const int beg = g_rowptr[n];
    const int end = g_rowptr[n + 1];
    if (lane == 0 && half == 0) g_fill[n] = 0;   // reset CSR fill counter for next replay

    float4 acc = make_float4(0.f, 0.f, 0.f, 0.f);
    int p = beg;
    if (gscale) {
        for (; p + 4 <= end; p += 4) {
            const int s0 = __ldg(&g_cols[p + 0]);
            const int s1 = __ldg(&g_cols[p + 1]);
            const int s2 = __ldg(&g_cols[p + 2]);
            const int s3 = __ldg(&g_cols[p + 3]);
            const float o0 = __ldg(&g_isout[s0]);
            const float o1 = __ldg(&g_isout[s1]);
            const float o2 = __ldg(&g_isout[s2]);
            const float o3 = __ldg(&g_isout[s3]);
            const float4 v0 = __ldg((const float4*)(g_z + (size_t)s0 * 256 + dbase));
            const float4 v1 = __ldg((const float4*)(g_z + (size_t)s1 * 256 + dbase));
            const float4 v2 = __ldg((const float4*)(g_z + (size_t)s2 * 256 + dbase));
            const float4 v3 = __ldg((const float4*)(g_z + (size_t)s3 * 256 + dbase));
            acc.x += fmaf(v0.x, o0, fmaf(v1.x, o1, fmaf(v2.x, o2, v3.x * o3)));
            acc.y += fmaf(v0.y, o0, fmaf(v1.y, o1, fmaf(v2.y, o2, v3.y * o3)));
            acc.z += fmaf(v0.z, o0, fmaf(v1.z, o1, fmaf(v2.z, o2, v3.z * o3)));
            acc.w += fmaf(v0.w, o0, fmaf(v1.w, o1, fmaf(v2.w, o2, v3.w * o3)));
        }
        for (; p < end; ++p) {
            const int s = __ldg(&g_cols[p]);
            const float o = __ldg(&g_isout[s]);
            const float4 v = __ldg((const float4*)(g_z + (size_t)s * 256 + dbase));
            acc.x = fmaf(v.x, o, acc.x); acc.y = fmaf(v.y, o, acc.y);
            acc.z = fmaf(v.z, o, acc.z); acc.w = fmaf(v.w, o, acc.w);
        }
    } else {
        for (; p + 4 <= end; p += 4) {
            const int s0 = __ldg(&g_cols[p + 0]);
            const int s1 = __ldg(&g_cols[p + 1]);
            const int s2 = __ldg(&g_cols[p + 2]);
            const int s3 = __ldg(&g_cols[p + 3]);
            const float4 v0 = __ldg((const float4*)(g_z + (size_t)s0 * 256 + dbase));
            const float4 v1 = __ldg((const float4*)(g_z + (size_t)s1 * 256 + dbase));
            const float4 v2 = __ldg((const float4*)(g_z + (size_t)s2 * 256 + dbase));
            const float4 v3 = __ldg((const float4*)(g_z + (size_t)s3 * 256 + dbase));
            acc.x += (v0.x + v1.x) + (v2.x + v3.x);
            acc.y += (v0.y + v1.y) + (v2.y + v3.y);
            acc.z += (v0.z + v1.z) + (v2.z + v3.z);
            acc.w += (v0.w + v1.w) + (v2.w + v3.w);
        }
        for (; p < end; ++p) {
            const int s = __ldg(&g_cols[p]);
            const float4 v = __ldg((const float4*)(g_z + (size_t)s * 256 + dbase));
            acc.x += v.x; acc.y += v.y; acc.z += v.z; acc.w += v.w;
        }
    }

    const float isn = g_isin[n];
    const float osc = g_isout[n];   // pre-scale for next layer's GEMM
    const float4 b4 = *(const float4*)(bias + dbase);
    float4 r;
    r.x = fmaxf(fmaf(acc.x, isn, b4.x), 0.f) * osc;
    r.y = fmaxf(fmaf(acc.y, isn, b4.y), 0.f) * osc;
    r.z = fmaxf(fmaf(acc.z, isn, b4.z), 0.f) * osc;
    r.w = fmaxf(fmaf(acc.w, isn, b4.w), 0.f) * osc;
    *(float4*)(g_h + (size_t)n * 256 + dbase) = r;
}

// ---------------- layer-3 SpMM (D=40) + log_softmax, warp-per-node ----------------
// Lanes 0..19 each own dims (2*lane, 2*lane+1) as a float2; gathers are coalesced
// 160B row reads. Max/sum reductions via full-warp shuffles; no smem, no syncs.
__global__ __launch_bounds__(256)
void spmm_logsoftmax_kernel(const float* __restrict__ bias, float* __restrict__ out)
{
    const int warp = threadIdx.x >> 5;
    const int lane = threadIdx.x & 31;
    const int n = blockIdx.x * 8 + warp;
    if (n >= NN) return;
    const bool act = (lane < DOUT / 2);   // lanes 0..19
    const int d0 = lane * 2;

    const int beg = g_rowptr[n];
    const int end = g_rowptr[n + 1];

    float2 acc = make_float2(0.f, 0.f);
    int p = beg;
    for (; p + 4 <= end; p += 4) {
        int s[4];
        #pragma unroll
        for (int q = 0; q < 4; q++) s[q] = __ldg(&g_cols[p + q]);
        if (act) {
            #pragma unroll
            for (int q = 0; q < 4; q++) {
                const float2 v = __ldg((const float2*)(g_z + (size_t)s[q] * DOUT + d0));
                acc.x += v.x; acc.y += v.y;
            }
        }
    }
    for (; p < end; ++p) {
        const int s = __ldg(&g_cols[p]);
        if (act) {
            const float2 v = __ldg((const float2*)(g_z + (size_t)s * DOUT + d0));
            acc.x += v.x; acc.y += v.y;
        }
    }

    const float isn = g_isin[n];
    float v0 = -INFINITY, v1 = -INFINITY;
    if (act) {
        v0 = fmaf(acc.x, isn, __ldg(&bias[d0]));
        v1 = fmaf(acc.y, isn, __ldg(&bias[d0 + 1]));
    }

    // warp max-reduce
    float mx = fmaxf(v0, v1);
    #pragma unroll
    for (int off = 16; off > 0; off >>= 1)
        mx = fmaxf(mx, __shfl_xor_sync(0xffffffffu, mx, off));

    // warp sum-reduce of exps
    float e = act ? (expf(v0 - mx) + expf(v1 - mx)) : 0.f;
    #pragma unroll
    for (int off = 16; off > 0; off >>= 1)
        e += __shfl_xor_sync(0xffffffffu, e, off);

    const float lse = mx + logf(e);
    if (act) {
        float2 r = make_float2(v0 - lse, v1 - lse);
        *(float2*)(out + (size_t)n * DOUT + d0) = r;
    }
}

// ---------------- launch ----------------
extern "C" void kernel_launch(void* const* d_in, const int* in_sizes, int n_in,
                              void* d_out, int out_size)
{
    const float* x  = (const float*)d_in[0];
    const float* W1 = (const float*)d_in[1];
    const float* b1 = (const float*)d_in[2];
    const float* W2 = (const float*)d_in[3];
    const float* b2 = (const float*)d_in[4];
    const float* W3 = (const float*)d_in[5];
    const float* b3 = (const float*)d_in[6];
    const int*  src = (const int*)d_in[7];
    const int*  dst = (const int*)d_in[8];
    float* out = (float*)d_out;

    // side stream + fork/join events (created once; resources, not work)
    static cudaStream_t s2 = nullptr;
    static cudaEvent_t ev_fork = nullptr, ev_join = nullptr;
    if (s2 == nullptr) {
        cudaStreamCreateWithFlags(&s2, cudaStreamNonBlocking);
        cudaEventCreateWithFlags(&ev_fork, cudaEventDisableTiming);
        cudaEventCreateWithFlags(&ev_join, cudaEventDisableTiming);
    }

    const int nb_e = (EE + 255) / 256;
    const int gm = (NN + 127) / 128;
    const int gw = (NN + 7) / 8;

    // fork: prep chain on s2, GEMM1 (no graph deps) on main stream
    cudaEventRecord(ev_fork, 0);
    cudaStreamWaitEvent(s2, ev_fork, 0);

    degree_kernel<<<nb_e, 256, 0, s2>>>(src, dst);
    scan_partial_kernel<<<NB_SCAN, 1024, 0, s2>>>();
    scan_mid_kernel<<<1, 32, 0, s2>>>();
    scan_final_kernel<<<NB_SCAN, 1024, 0, s2>>>();
    csr_fill_kernel<<<nb_e, 256, 0, s2>>>(src, dst);
    cudaEventRecord(ev_join, s2);

    gemm_kernel<<<dim3(2, gm), 256>>>(x, 1, W1, NN, 256);   // z1 = x @ W1

    // join: SpMM1 needs both z1 and the graph
    cudaStreamWaitEvent(0, ev_join, 0);

    // layer 1: h1 = relu(isin * sum isout[s]*z1[s] + b1) * isout
    spmm_warp_kernel<<<gw, 256>>>(b1, 0, 1);
    spmm_warp_kernel<<<gw, 256>>>(b1, 1, 1);

    // layer 2: z2 = h1 @ W2 ; h2 = relu(isin * sum z2[s] + b2) * isout
    gemm_kernel<<<dim3(2, gm), 256>>>(x, 0, W2, NN, 256);
    spmm_warp_kernel<<<gw, 256>>>(b2, 0, 0);
    spmm_warp_kernel<<<gw, 256>>>(b2, 1, 0);

    // layer 3: z3 = h2 @ W3 ; out = log_softmax(isin * sum z3[s] + b3)
    gemm64_kernel<<<gm, 128>>>(W3, NN, DOUT);
    spmm_logsoftmax_kernel<<<gw, 256>>>(b3, out);
}

// round 15
// speedup vs baseline: 1.0988x; 1.0332x over previous
#include <cuda_runtime.h>
#include <math.h>
#include <stdint.h>

#define NN 100000
#define EE 1600000
#define DHID 256
#define DOUT 40
#define NB_SCAN ((NN + 1023) / 1024)

// ---------------- scratch (device globals; zero-initialized at module load) ----------------
__device__ int   g_outdeg[NN];
__device__ int   g_indeg[NN];
__device__ float g_isout[NN];
__device__ float g_isin[NN];
__device__ int   g_rowptr[NN + 1];
__device__ int   g_fill[NN];
__device__ int   g_bsum[NB_SCAN + 1];
__device__ int   g_cols[EE];
__device__ float g_z[(size_t)NN * DHID];   // GEMM output
__device__ float g_h[(size_t)NN * DHID];   // SpMM output, PRE-SCALED by isout

// ---------------- graph prep ----------------
__global__ void degree_kernel(const int* __restrict__ src, const int* __restrict__ dst) {
    int e = blockIdx.x * blockDim.x + threadIdx.x;
    if (e < EE) {
        atomicAdd(&g_outdeg[src[e]], 1);
        atomicAdd(&g_indeg[dst[e]], 1);
    }
}

__global__ void scan_partial_kernel() {
    __shared__ int ws[32];
    const int b = blockIdx.x, tid = threadIdx.x;
    const int i = b * 1024 + tid;
    int x = (i < NN) ? g_indeg[i] : 0;
    #pragma unroll
    for (int off = 16; off > 0; off >>= 1) x += __shfl_down_sync(0xffffffffu, x, off);
    if ((tid & 31) == 0) ws[tid >> 5] = x;
    __syncthreads();
    if (tid < 32) {
        int w = ws[tid];
        #pragma unroll
        for (int off = 16; off > 0; off >>= 1) w += __shfl_down_sync(0xffffffffu, w, off);
        if (tid == 0) g_bsum[b] = w;
    }
}

__global__ void scan_mid_kernel() {
    if (threadIdx.x == 0) {
        int run = 0;
        for (int b = 0; b < NB_SCAN; b++) { int t = g_bsum[b]; g_bsum[b] = run; run += t; }
        g_rowptr[NN] = run;
    }
}

__global__ void scan_final_kernel() {
    __shared__ int ws[32];
    const int b = blockIdx.x, tid = threadIdx.x;
    const int lane = tid & 31, wid = tid >> 5;
    const int i = b * 1024 + tid;
    const int v = (i < NN) ? g_indeg[i] : 0;
    int x = v;
    #pragma unroll
    for (int off = 1; off < 32; off <<= 1) {
        int y = __shfl_up_sync(0xffffffffu, x, off);
        if (lane >= off) x += y;
    }
    if (lane == 31) ws[wid] = x;
    __syncthreads();
    if (wid == 0) {
        int w = ws[lane];
        #pragma unroll
        for (int off = 1; off < 32; off <<= 1) {
            int y = __shfl_up_sync(0xffffffffu, w, off);
            if (lane >= off) w += y;
        }
        ws[lane] = w;
    }
    __syncthreads();
    int incl = x + ((wid > 0) ? ws[wid - 1] : 0);
    if (i < NN) {
        g_rowptr[i] = g_bsum[b] + incl - v;
        int od = g_outdeg[i];
        g_isout[i] = (od > 0) ? rsqrtf((float)od) : 0.f;
        g_isin[i]  = (v > 0) ? rsqrtf((float)v) : 0.f;
        g_indeg[i]  = 0;
        g_outdeg[i] = 0;
    }
}

__global__ void csr_fill_kernel(const int* __restrict__ src, const int* __restrict__ dst) {
    int e = blockIdx.x * blockDim.x + threadIdx.x;
    if (e < EE) {
        int d = dst[e];
        int p = g_rowptr[d] + atomicAdd(&g_fill[d], 1);
        g_cols[p] = src[e];
    }
}

// ---------------- GEMM: g_z[r,c] = sum_k A[r,k] * W[k,c]  (NO row scaling) ----------------
#define FMA2(d, a, b) asm("fma.rn.f32x2 %0, %1, %2, %0;" : "+l"(d) : "l"(a), "l"(b))

__global__ __launch_bounds__(256, 2)
void gemm_kernel(const float* __restrict__ Xin, int use_x,
                 const float* __restrict__ W, int nrows, int ncols)
{
    const float* __restrict__ A = use_x ? Xin : (const float*)g_h;
    __shared__ float As[16][128];                 // [k][m]
    __shared__ unsigned long long BdS[16][128];   // [k][swizzled pair slot]

    const int tid = threadIdx.x;
    const int tx = tid & 15, ty = tid >> 4;
    const int rowBase = blockIdx.y * 128;
    const int colBase = blockIdx.x * 128;

    const int lr = tid >> 1;
    const int lk = (tid & 1) * 8;
    const int arow = rowBase + lr;

    const int bk  = tid >> 4;
    const int btx = tid & 15;
    const int bc0 = colBase + btx * 8;

    unsigned long long acc[4][8];
    #pragma unroll
    for (int i = 0; i < 4; i++)
        #pragma unroll
        for (int j = 0; j < 8; j++) acc[i][j] = 0ull;

    for (int k0 = 0; k0 < 256; k0 += 16) {
        float4 a0 = make_float4(0.f, 0.f, 0.f, 0.f), a1 = a0;
        if (arow < nrows) {
            const float4* Ar = reinterpret_cast<const float4*>(A + (size_t)arow * 256);
            a0 = Ar[(k0 + lk) >> 2];
            a1 = Ar[(k0 + lk + 4) >> 2];
        }
        As[lk + 0][lr] = a0.x; As[lk + 1][lr] = a0.y;
        As[lk + 2][lr] = a0.z; As[lk + 3][lr] = a0.w;
        As[lk + 4][lr] = a1.x; As[lk + 5][lr] = a1.y;
        As[lk + 6][lr] = a1.z; As[lk + 7][lr] = a1.w;

        float bv[8];
        {
            const float* Wr = &W[(size_t)(k0 + bk) * ncols + bc0];
            float4 w0 = *reinterpret_cast<const float4*>(Wr);
            float4 w1 = *reinterpret_cast<const float4*>(Wr + 4);
            bv[0] = w0.x; bv[1] = w0.y; bv[2] = w0.z; bv[3] = w0.w;
            bv[4] = w1.x; bv[5] = w1.y; bv[6] = w1.z; bv[7] = w1.w;
        }
        #pragma unroll
        for (int m = 0; m < 8; m++) {
            unsigned int b = __float_as_uint(bv[m]);
            unsigned long long pv = ((unsigned long long)b << 32) | (unsigned long long)b;
            BdS[bk][m * 16 + btx] = pv;
        }
        __syncthreads();

        #pragma unroll
        for (int kk = 0; kk < 16; kk++) {
            unsigned long long a2[4], bd[8];
            #pragma unroll
            for (int i = 0; i < 4; i++)
                a2[i] = *reinterpret_cast<const unsigned long long*>(&As[kk][ty * 8 + 2 * i]);
            #pragma unroll
            for (int j = 0; j < 8; j++)
                bd[j] = BdS[kk][j * 16 + tx];
            #pragma unroll
            for (int i = 0; i < 4; i++)
                #pragma unroll
                for (int j = 0; j < 8; j++)
                    FMA2(acc[i][j], a2[i], bd[j]);
        }
        __syncthreads();
    }

    const int c0 = colBase + tx * 8;
    #pragma unroll
    for (int i = 0; i < 4; i++) {
        #pragma unroll
        for (int h = 0; h < 2; h++) {
            int r = rowBase + ty * 8 + 2 * i + h;
            if (r >= nrows) continue;
            float vals[8];
            #pragma unroll
            for (int j = 0; j < 8; j++) {
                unsigned long long p = acc[i][j];
                unsigned int bits = h ? (unsigned int)(p >> 32) : (unsigned int)p;
                vals[j] = __uint_as_float(bits);
            }
            float* zr = &g_z[(size_t)r * ncols + c0];
            *reinterpret_cast<float4*>(zr)     = make_float4(vals[0], vals[1], vals[2], vals[3]);
            *reinterpret_cast<float4*>(zr + 4) = make_float4(vals[4], vals[5], vals[6], vals[7]);
        }
    }
}

// ---------------- layer-3 GEMM: exactly 40 columns, no padding waste ----------------
// 128 threads: tx=tid&7 covers cols {j*8+tx : j<5} (all 40), ty=tid>>3 covers rows.
// BdS[kk][j*8+tx] read: word (16j+2tx) mod 32 -> 8 distinct bank pairs, 4-way
// ty-broadcast -> conflict-free.
__global__ __launch_bounds__(128, 4)
void gemm40_kernel(const float* __restrict__ W, int nrows)
{
    const float* __restrict__ A = (const float*)g_h;
    __shared__ float As[16][128];
    __shared__ unsigned long long BdS[16][40];

    const int tid = threadIdx.x;
    const int tx = tid & 7, ty = tid >> 3;
    const int rowBase = blockIdx.x * 128;

    const int lr = tid;
    const int arow = rowBase + lr;

    const int bk  = tid >> 3;   // 0..15
    const int btx = tid & 7;    // 0..7

    unsigned long long acc[4][5];
    #pragma unroll
    for (int i = 0; i < 4; i++)
        #pragma unroll
        for (int j = 0; j < 5; j++) acc[i][j] = 0ull;

    for (int k0 = 0; k0 < 256; k0 += 16) {
        if (arow < nrows) {
            const float4* Ar = reinterpret_cast<const float4*>(A + (size_t)arow * 256);
            #pragma unroll
            for (int q = 0; q < 4; q++) {
                float4 a = Ar[(k0 >> 2) + q];
                As[q * 4 + 0][lr] = a.x;
                As[q * 4 + 1][lr] = a.y;
                As[q * 4 + 2][lr] = a.z;
                As[q * 4 + 3][lr] = a.w;
            }
        } else {
            #pragma unroll
            for (int q = 0; q < 16; q++) As[q][lr] = 0.f;
        }
        // B: thread (bk, btx) loads cols {j*8+btx : j<5} of W row k0+bk
        #pragma unroll
        for (int j = 0; j < 5; j++) {
            const int col = j * 8 + btx;
            unsigned int b = __float_as_uint(W[(size_t)(k0 + bk) * DOUT + col]);
            BdS[bk][col] = ((unsigned long long)b << 32) | (unsigned long long)b;
        }
        __syncthreads();

        #pragma unroll
        for (int kk = 0; kk < 16; kk++) {
            unsigned long long a2[4], bd[5];
            #pragma unroll
            for (int i = 0; i < 4; i++)
                a2[i] = *reinterpret_cast<const unsigned long long*>(&As[kk][ty * 8 + 2 * i]);
            #pragma unroll
            for (int j = 0; j < 5; j++)
                bd[j] = BdS[kk][j * 8 + tx];
            #pragma unroll
            for (int i = 0; i < 4; i++)
                #pragma unroll
                for (int j = 0; j < 5; j++)
                    FMA2(acc[i][j], a2[i], bd[j]);
        }
        __syncthreads();
    }

    #pragma unroll
    for (int i = 0; i < 4; i++) {
        #pragma unroll
        for (int h = 0; h < 2; h++) {
            int r = rowBase + ty * 8 + 2 * i + h;
            if (r >= nrows) continue;
            #pragma unroll
            for (int j = 0; j < 5; j++) {
                unsigned long long p = acc[i][j];
                unsigned int bits = h ? (unsigned int)(p >> 32) : (unsigned int)p;
                g_z[(size_t)r * DOUT + j * 8 + tx] = __uint_as_float(bits);
            }
        }
    }
}

// ---------------- SpMM gather, warp-per-node, feature-split, 4-edge, isout at gather ----------------
// Layer 1 only: g_h[n,d] = relu(isin[n]*sum isout[s]*z[s,d] + b[d]) * isout[n].
__global__ __launch_bounds__(256)
void spmm_warp_kernel(const float* __restrict__ bias, int half)
{
    const int warp = threadIdx.x >> 5;
    const int lane = threadIdx.x & 31;
    const int n = blockIdx.x * 8 + warp;
    if (n >= NN) return;
    const int dbase = half * 128 + lane * 4;

    const int beg = g_rowptr[n];
    const int end = g_rowptr[n + 1];
    if (lane == 0 && half == 0) g_fill[n] = 0;   // reset CSR fill counter for next replay

    float4 acc = make_float4(0.f, 0.f, 0.f, 0.f);
    int p = beg;
    for (; p + 4 <= end; p += 4) {
        const int s0 = __ldg(&g_cols[p + 0]);
        const int s1 = __ldg(&g_cols[p + 1]);
        const int s2 = __ldg(&g_cols[p + 2]);
        const int s3 = __ldg(&g_cols[p + 3]);
        const float o0 = __ldg(&g_isout[s0]);
        const float o1 = __ldg(&g_isout[s1]);
        const float o2 = __ldg(&g_isout[s2]);
        const float o3 = __ldg(&g_isout[s3]);
        const float4 v0 = __ldg((const float4*)(g_z + (size_t)s0 * 256 + dbase));
        const float4 v1 = __ldg((const float4*)(g_z + (size_t)s1 * 256 + dbase));
        const float4 v2 = __ldg((const float4*)(g_z + (size_t)s2 * 256 + dbase));
        const float4 v3 = __ldg((const float4*)(g_z + (size_t)s3 * 256 + dbase));
        acc.x += fmaf(v0.x, o0, fmaf(v1.x, o1, fmaf(v2.x, o2, v3.x * o3)));
        acc.y += fmaf(v0.y, o0, fmaf(v1.y, o1, fmaf(v2.y, o2, v3.y * o3)));
        acc.z += fmaf(v0.z, o0, fmaf(v1.z, o1, fmaf(v2.z, o2, v3.z * o3)));
        acc.w += fmaf(v0.w, o0, fmaf(v1.w, o1, fmaf(v2.w, o2, v3.w * o3)));
    }
    for (; p < end; ++p) {
        const int s = __ldg(&g_cols[p]);
        const float o = __ldg(&g_isout[s]);
        const float4 v = __ldg((const float4*)(g_z + (size_t)s * 256 + dbase));
        acc.x = fmaf(v.x, o, acc.x); acc.y = fmaf(v.y, o, acc.y);
        acc.z = fmaf(v.z, o, acc.z); acc.w = fmaf(v.w, o, acc.w);
    }

    const float isn = g_isin[n];
    const float osc = g_isout[n];
    const float4 b4 = *(const float4*)(bias + dbase);
    float4 r;
    r.x = fmaxf(fmaf(acc.x, isn, b4.x), 0.f) * osc;
    r.y = fmaxf(fmaf(acc.y, isn, b4.y), 0.f) * osc;
    r.z = fmaxf(fmaf(acc.z, isn, b4.z), 0.f) * osc;
    r.w = fmaxf(fmaf(acc.w, isn, b4.w), 0.f) * osc;
    *(float4*)(g_h + (size_t)n * 256 + dbase) = r;
}

// ---------------- SpMM gather, plain (no gscale), 8-edge unroll — layer 2 ----------------
// Separate kernel so its register allocation isn't burdened by the gscale path.
__global__ __launch_bounds__(256)
void spmm_warp8_kernel(const float* __restrict__ bias, int half)
{
    const int warp = threadIdx.x >> 5;
    const int lane = threadIdx.x & 31;
    const int n = blockIdx.x * 8 + warp;
    if (n >= NN) return;
    const int dbase = half * 128 + lane * 4;

    const int beg = g_rowptr[n];
    const int end = g_rowptr[n + 1];

    float4 acc = make_float4(0.f, 0.f, 0.f, 0.f);
    int p = beg;
    for (; p + 8 <= end; p += 8) {
        int s[8];
        #pragma unroll
        for (int q = 0; q < 8; q++) s[q] = __ldg(&g_cols[p + q]);
        float4 v[8];
        #pragma unroll
        for (int q = 0; q < 8; q++)
            v[q] = __ldg((const float4*)(g_z + (size_t)s[q] * 256 + dbase));
        acc.x += ((v[0].x + v[1].x) + (v[2].x + v[3].x)) + ((v[4].x + v[5].x) + (v[6].x + v[7].x));
        acc.y += ((v[0].y + v[1].y) + (v[2].y + v[3].y)) + ((v[4].y + v[5].y) + (v[6].y + v[7].y));
        acc.z += ((v[0].z + v[1].z) + (v[2].z + v[3].z)) + ((v[4].z + v[5].z) + (v[6].z + v[7].z));
        acc.w += ((v[0].w + v[1].w) + (v[2].w + v[3].w)) + ((v[4].w + v[5].w) + (v[6].w + v[7].w));
    }
    for (; p + 4 <= end; p += 4) {
        const int s0 = __ldg(&g_cols[p + 0]);
        const int s1 = __ldg(&g_cols[p + 1]);
        const int s2 = __ldg(&g_cols[p + 2]);
        const int s3 = __ldg(&g_cols[p + 3]);
        const float4 v0 = __ldg((const float4*)(g_z + (size_t)s0 * 256 + dbase));
        const float4 v1 = __ldg((const float4*)(g_z + (size_t)s1 * 256 + dbase));
        const float4 v2 = __ldg((const float4*)(g_z + (size_t)s2 * 256 + dbase));
        const float4 v3 = __ldg((const float4*)(g_z + (size_t)s3 * 256 + dbase));
        acc.x += (v0.x + v1.x) + (v2.x + v3.x);
        acc.y += (v0.y + v1.y) + (v2.y + v3.y);
        acc.z += (v0.z + v1.z) + (v2.z + v3.z);
        acc.w += (v0.w + v1.w) + (v2.w + v3.w);
    }
    for (; p < end; ++p) {
        const int s = __ldg(&g_cols[p]);
        const float4 v = __ldg((const float4*)(g_z + (size_t)s * 256 + dbase));
        acc.x += v.x; acc.y += v.y; acc.z += v.z; acc.w += v.w;
    }

    const float isn = g_isin[n];
    const float osc = g_isout[n];
    const float4 b4 = *(const float4*)(bias + dbase);
    float4 r;
    r.x = fmaxf(fmaf(acc.x, isn, b4.x), 0.f) * osc;
    r.y = fmaxf(fmaf(acc.y, isn, b4.y), 0.f) * osc;
    r.z = fmaxf(fmaf(acc.z, isn, b4.z), 0.f) * osc;
    r.w = fmaxf(fmaf(acc.w, isn, b4.w), 0.f) * osc;
    *(float4*)(g_h + (size_t)n * 256 + dbase) = r;
}

// ---------------- layer-3 SpMM (D=40) + log_softmax, warp-per-node ----------------
__global__ __launch_bounds__(256)
void spmm_logsoftmax_kernel(const float* __restrict__ bias, float* __restrict__ out)
{
    const int warp = threadIdx.x >> 5;
    const int lane = threadIdx.x & 31;
    const int n = blockIdx.x * 8 + warp;
    if (n >= NN) return;
    const bool act = (lane < DOUT / 2);   // lanes 0..19
    const int d0 = lane * 2;

    const int beg = g_rowptr[n];
    const int end = g_rowptr[n + 1];

    float2 acc = make_float2(0.f, 0.f);
    int p = beg;
    for (; p + 4 <= end; p += 4) {
        int s[4];
        #pragma unroll
        for (int q = 0; q < 4; q++) s[q] = __ldg(&g_cols[p + q]);
        if (act) {
            #pragma unroll
            for (int q = 0; q < 4; q++) {
                const float2 v = __ldg((const float2*)(g_z + (size_t)s[q] * DOUT + d0));
                acc.x += v.x; acc.y += v.y;
            }
        }
    }
    for (; p < end; ++p) {
        const int s = __ldg(&g_cols[p]);
        if (act) {
            const float2 v = __ldg((const float2*)(g_z + (size_t)s * DOUT + d0));
            acc.x += v.x; acc.y += v.y;
        }
    }

    const float isn = g_isin[n];
    float v0 = -INFINITY, v1 = -INFINITY;
    if (act) {
        v0 = fmaf(acc.x, isn, __ldg(&bias[d0]));
        v1 = fmaf(acc.y, isn, __ldg(&bias[d0 + 1]));
    }

    float mx = fmaxf(v0, v1);
    #pragma unroll
    for (int off = 16; off > 0; off >>= 1)
        mx = fmaxf(mx, __shfl_xor_sync(0xffffffffu, mx, off));

    float e = act ? (expf(v0 - mx) + expf(v1 - mx)) : 0.f;
    #pragma unroll
    for (int off = 16; off > 0; off >>= 1)
        e += __shfl_xor_sync(0xffffffffu, e, off);

    const float lse = mx + logf(e);
    if (act) {
        float2 r = make_float2(v0 - lse, v1 - lse);
        *(float2*)(out + (size_t)n * DOUT + d0) = r;
    }
}

// ---------------- launch ----------------
extern "C" void kernel_launch(void* const* d_in, const int* in_sizes, int n_in,
                              void* d_out, int out_size)
{
    const float* x  = (const float*)d_in[0];
    const float* W1 = (const float*)d_in[1];
    const float* b1 = (const float*)d_in[2];
    const float* W2 = (const float*)d_in[3];
    const float* b2 = (const float*)d_in[4];
    const float* W3 = (const float*)d_in[5];
    const float* b3 = (const float*)d_in[6];
    const int*  src = (const int*)d_in[7];
    const int*  dst = (const int*)d_in[8];
    float* out = (float*)d_out;

    // side stream + fork/join events (created once; resources, not work)
    static cudaStream_t s2 = nullptr;
    static cudaEvent_t ev_fork = nullptr, ev_join = nullptr;
    if (s2 == nullptr) {
        cudaStreamCreateWithFlags(&s2, cudaStreamNonBlocking);
        cudaEventCreateWithFlags(&ev_fork, cudaEventDisableTiming);
        cudaEventCreateWithFlags(&ev_join, cudaEventDisableTiming);
    }

    const int nb_e = (EE + 255) / 256;
    const int gm = (NN + 127) / 128;
    const int gw = (NN + 7) / 8;

    // fork: prep chain on s2, GEMM1 (no graph deps) on main stream
    cudaEventRecord(ev_fork, 0);
    cudaStreamWaitEvent(s2, ev_fork, 0);

    degree_kernel<<<nb_e, 256, 0, s2>>>(src, dst);
    scan_partial_kernel<<<NB_SCAN, 1024, 0, s2>>>();
    scan_mid_kernel<<<1, 32, 0, s2>>>();
    scan_final_kernel<<<NB_SCAN, 1024, 0, s2>>>();
    csr_fill_kernel<<<nb_e, 256, 0, s2>>>(src, dst);
    cudaEventRecord(ev_join, s2);

    gemm_kernel<<<dim3(2, gm), 256>>>(x, 1, W1, NN, 256);   // z1 = x @ W1

    cudaStreamWaitEvent(0, ev_join, 0);

    // layer 1: h1 = relu(isin * sum isout[s]*z1[s] + b1) * isout
    spmm_warp_kernel<<<gw, 256>>>(b1, 0);
    spmm_warp_kernel<<<gw, 256>>>(b1, 1);

    // layer 2: z2 = h1 @ W2 ; h2 = relu(isin * sum z2[s] + b2) * isout
    gemm_kernel<<<dim3(2, gm), 256>>>(x, 0, W2, NN, 256);
    spmm_warp8_kernel<<<gw, 256>>>(b2, 0);
    spmm_warp8_kernel<<<gw, 256>>>(b2, 1);

    // layer 3: z3 = h2 @ W3 (exact 40 cols) ; out = log_softmax(isin * sum z3[s] + b3)
    gemm40_kernel<<<gm, 128>>>(W3, NN);
    spmm_logsoftmax_kernel<<<gw, 256>>>(b3, out);
}

// round 16
// speedup vs baseline: 1.1040x; 1.0047x over previous
#include <cuda_runtime.h>
#include <math.h>
#include <stdint.h>

#define NN 100000
#define EE 1600000
#define DHID 256
#define DOUT 40
#define NB_SCAN ((NN + 1023) / 1024)

// ---------------- scratch (device globals; zero-initialized at module load) ----------------
__device__ int   g_outdeg[NN];
__device__ int   g_indeg[NN];
__device__ float g_isout[NN];
__device__ float g_isin[NN];
__device__ int   g_rowptr[NN + 1];
__device__ int   g_fill[NN];
__device__ int   g_bsum[NB_SCAN + 1];
__device__ int   g_cols[EE];
__device__ float g_z[(size_t)NN * DHID];   // GEMM output
__device__ float g_h[(size_t)NN * DHID];   // SpMM output, PRE-SCALED by isout

// ---------------- graph prep ----------------
__global__ void degree_kernel(const int* __restrict__ src, const int* __restrict__ dst) {
    int e = blockIdx.x * blockDim.x + threadIdx.x;
    if (e < EE) {
        atomicAdd(&g_outdeg[src[e]], 1);
        atomicAdd(&g_indeg[dst[e]], 1);
    }
}

__global__ void scan_partial_kernel() {
    __shared__ int ws[32];
    const int b = blockIdx.x, tid = threadIdx.x;
    const int i = b * 1024 + tid;
    int x = (i < NN) ? g_indeg[i] : 0;
    #pragma unroll
    for (int off = 16; off > 0; off >>= 1) x += __shfl_down_sync(0xffffffffu, x, off);
    if ((tid & 31) == 0) ws[tid >> 5] = x;
    __syncthreads();
    if (tid < 32) {
        int w = ws[tid];
        #pragma unroll
        for (int off = 16; off > 0; off >>= 1) w += __shfl_down_sync(0xffffffffu, w, off);
        if (tid == 0) g_bsum[b] = w;
    }
}

__global__ void scan_mid_kernel() {
    if (threadIdx.x == 0) {
        int run = 0;
        for (int b = 0; b < NB_SCAN; b++) { int t = g_bsum[b]; g_bsum[b] = run; run += t; }
        g_rowptr[NN] = run;
    }
}

__global__ void scan_final_kernel() {
    __shared__ int ws[32];
    const int b = blockIdx.x, tid = threadIdx.x;
    const int lane = tid & 31, wid = tid >> 5;
    const int i = b * 1024 + tid;
    const int v = (i < NN) ? g_indeg[i] : 0;
    int x = v;
    #pragma unroll
    for (int off = 1; off < 32; off <<= 1) {
        int y = __shfl_up_sync(0xffffffffu, x, off);
        if (lane >= off) x += y;
    }
    if (lane == 31) ws[wid] = x;
    __syncthreads();
    if (wid == 0) {
        int w = ws[lane];
        #pragma unroll
        for (int off = 1; off < 32; off <<= 1) {
            int y = __shfl_up_sync(0xffffffffu, w, off);
            if (lane >= off) w += y;
        }
        ws[lane] = w;
    }
    __syncthreads();
    int incl = x + ((wid > 0) ? ws[wid - 1] : 0);
    if (i < NN) {
        g_rowptr[i] = g_bsum[b] + incl - v;
        int od = g_outdeg[i];
        g_isout[i] = (od > 0) ? rsqrtf((float)od) : 0.f;
        g_isin[i]  = (v > 0) ? rsqrtf((float)v) : 0.f;
        g_indeg[i]  = 0;
        g_outdeg[i] = 0;
    }
}

__global__ void csr_fill_kernel(const int* __restrict__ src, const int* __restrict__ dst) {
    int e = blockIdx.x * blockDim.x + threadIdx.x;
    if (e < EE) {
        int d = dst[e];
        int p = g_rowptr[d] + atomicAdd(&g_fill[d], 1);
        g_cols[p] = src[e];
    }
}

// ---------------- GEMM: one 128-col block per launch: g_z[:, colblk*128 ..] ----------------
#define FMA2(d, a, b) asm("fma.rn.f32x2 %0, %1, %2, %0;" : "+l"(d) : "l"(a), "l"(b))

__global__ __launch_bounds__(256, 2)
void gemm_kernel(const float* __restrict__ Xin, int use_x,
                 const float* __restrict__ W, int nrows, int ncols, int colblk)
{
    const float* __restrict__ A = use_x ? Xin : (const float*)g_h;
    __shared__ float As[16][128];                 // [k][m]
    __shared__ unsigned long long BdS[16][128];   // [k][swizzled pair slot]

    const int tid = threadIdx.x;
    const int tx = tid & 15, ty = tid >> 4;
    const int rowBase = blockIdx.x * 128;
    const int colBase = colblk * 128;

    const int lr = tid >> 1;
    const int lk = (tid & 1) * 8;
    const int arow = rowBase + lr;

    const int bk  = tid >> 4;
    const int btx = tid & 15;
    const int bc0 = colBase + btx * 8;

    unsigned long long acc[4][8];
    #pragma unroll
    for (int i = 0; i < 4; i++)
        #pragma unroll
        for (int j = 0; j < 8; j++) acc[i][j] = 0ull;

    for (int k0 = 0; k0 < 256; k0 += 16) {
        float4 a0 = make_float4(0.f, 0.f, 0.f, 0.f), a1 = a0;
        if (arow < nrows) {
            const float4* Ar = reinterpret_cast<const float4*>(A + (size_t)arow * 256);
            a0 = Ar[(k0 + lk) >> 2];
            a1 = Ar[(k0 + lk + 4) >> 2];
        }
        As[lk + 0][lr] = a0.x; As[lk + 1][lr] = a0.y;
        As[lk + 2][lr] = a0.z; As[lk + 3][lr] = a0.w;
        As[lk + 4][lr] = a1.x; As[lk + 5][lr] = a1.y;
        As[lk + 6][lr] = a1.z; As[lk + 7][lr] = a1.w;

        float bv[8];
        {
            const float* Wr = &W[(size_t)(k0 + bk) * ncols + bc0];
            float4 w0 = *reinterpret_cast<const float4*>(Wr);
            float4 w1 = *reinterpret_cast<const float4*>(Wr + 4);
            bv[0] = w0.x; bv[1] = w0.y; bv[2] = w0.z; bv[3] = w0.w;
            bv[4] = w1.x; bv[5] = w1.y; bv[6] = w1.z; bv[7] = w1.w;
        }
        #pragma unroll
        for (int m = 0; m < 8; m++) {
            unsigned int b = __float_as_uint(bv[m]);
            unsigned long long pv = ((unsigned long long)b << 32) | (unsigned long long)b;
            BdS[bk][m * 16 + btx] = pv;
        }
        __syncthreads();

        #pragma unroll
        for (int kk = 0; kk < 16; kk++) {
            unsigned long long a2[4], bd[8];
            #pragma unroll
            for (int i = 0; i < 4; i++)
                a2[i] = *reinterpret_cast<const unsigned long long*>(&As[kk][ty * 8 + 2 * i]);
            #pragma unroll
            for (int j = 0; j < 8; j++)
                bd[j] = BdS[kk][j * 16 + tx];
            #pragma unroll
            for (int i = 0; i < 4; i++)
                #pragma unroll
                for (int j = 0; j < 8; j++)
                    FMA2(acc[i][j], a2[i], bd[j]);
        }
        __syncthreads();
    }

    const int c0 = colBase + tx * 8;
    #pragma unroll
    for (int i = 0; i < 4; i++) {
        #pragma unroll
        for (int h = 0; h < 2; h++) {
            int r = rowBase + ty * 8 + 2 * i + h;
            if (r >= nrows) continue;
            float vals[8];
            #pragma unroll
            for (int j = 0; j < 8; j++) {
                unsigned long long p = acc[i][j];
                unsigned int bits = h ? (unsigned int)(p >> 32) : (unsigned int)p;
                vals[j] = __uint_as_float(bits);
            }
            float* zr = &g_z[(size_t)r * ncols + c0];
            *reinterpret_cast<float4*>(zr)     = make_float4(vals[0], vals[1], vals[2], vals[3]);
            *reinterpret_cast<float4*>(zr + 4) = make_float4(vals[4], vals[5], vals[6], vals[7]);
        }
    }
}

// ---------------- layer-3 GEMM: exactly 40 columns ----------------
__global__ __launch_bounds__(128, 4)
void gemm40_kernel(const float* __restrict__ W, int nrows)
{
    const float* __restrict__ A = (const float*)g_h;
    __shared__ float As[16][128];
    __shared__ unsigned long long BdS[16][40];

    const int tid = threadIdx.x;
    const int tx = tid & 7, ty = tid >> 3;
    const int rowBase = blockIdx.x * 128;

    const int lr = tid;
    const int arow = rowBase + lr;

    const int bk  = tid >> 3;
    const int btx = tid & 7;

    unsigned long long acc[4][5];
    #pragma unroll
    for (int i = 0; i < 4; i++)
        #pragma unroll
        for (int j = 0; j < 5; j++) acc[i][j] = 0ull;

    for (int k0 = 0; k0 < 256; k0 += 16) {
        if (arow < nrows) {
            const float4* Ar = reinterpret_cast<const float4*>(A + (size_t)arow * 256);
            #pragma unroll
            for (int q = 0; q < 4; q++) {
                float4 a = Ar[(k0 >> 2) + q];
                As[q * 4 + 0][lr] = a.x;
                As[q * 4 + 1][lr] = a.y;
                As[q * 4 + 2][lr] = a.z;
                As[q * 4 + 3][lr] = a.w;
            }
        } else {
            #pragma unroll
            for (int q = 0; q < 16; q++) As[q][lr] = 0.f;
        }
        #pragma unroll
        for (int j = 0; j < 5; j++) {
            const int col = j * 8 + btx;
            unsigned int b = __float_as_uint(W[(size_t)(k0 + bk) * DOUT + col]);
            BdS[bk][col] = ((unsigned long long)b << 32) | (unsigned long long)b;
        }
        __syncthreads();

        #pragma unroll
        for (int kk = 0; kk < 16; kk++) {
            unsigned long long a2[4], bd[5];
            #pragma unroll
            for (int i = 0; i < 4; i++)
                a2[i] = *reinterpret_cast<const unsigned long long*>(&As[kk][ty * 8 + 2 * i]);
            #pragma unroll
            for (int j = 0; j < 5; j++)
                bd[j] = BdS[kk][j * 8 + tx];
            #pragma unroll
            for (int i = 0; i < 4; i++)
                #pragma unroll
                for (int j = 0; j < 5; j++)
                    FMA2(acc[i][j], a2[i], bd[j]);
        }
        __syncthreads();
    }

    #pragma unroll
    for (int i = 0; i < 4; i++) {
        #pragma unroll
        for (int h = 0; h < 2; h++) {
            int r = rowBase + ty * 8 + 2 * i + h;
            if (r >= nrows) continue;
            #pragma unroll
            for (int j = 0; j < 5; j++) {
                unsigned long long p = acc[i][j];
                unsigned int bits = h ? (unsigned int)(p >> 32) : (unsigned int)p;
                g_z[(size_t)r * DOUT + j * 8 + tx] = __uint_as_float(bits);
            }
        }
    }
}

// ---------------- layer-1 SpMM: warp-per-node, 4-edge, isout at gather ----------------
__global__ __launch_bounds__(256)
void spmm_warp_kernel(const float* __restrict__ bias, int half)
{
    const int warp = threadIdx.x >> 5;
    const int lane = threadIdx.x & 31;
    const int n = blockIdx.x * 8 + warp;
    if (n >= NN) return;
    const int dbase = half * 128 + lane * 4;

    const int beg = g_rowptr[n];
    const int end = g_rowptr[n + 1];
    if (lane == 0 && half == 0) g_fill[n] = 0;   // reset CSR fill counter for next replay

    float4 acc = make_float4(0.f, 0.f, 0.f, 0.f);
    int p = beg;
    for (; p + 4 <= end; p += 4) {
        const int s0 = __ldg(&g_cols[p + 0]);
        const int s1 = __ldg(&g_cols[p + 1]);
        const int s2 = __ldg(&g_cols[p + 2]);
        const int s3 = __ldg(&g_cols[p + 3]);
        const float o0 = __ldg(&g_isout[s0]);
        const float o1 = __ldg(&g_isout[s1]);
        const float o2 = __ldg(&g_isout[s2]);
        const float o3 = __ldg(&g_isout[s3]);
        const float4 v0 = __ldg((const float4*)(g_z + (size_t)s0 * 256 + dbase));
        const float4 v1 = __ldg((const float4*)(g_z + (size_t)s1 * 256 + dbase));
        const float4 v2 = __ldg((const float4*)(g_z + (size_t)s2 * 256 + dbase));
        const float4 v3 = __ldg((const float4*)(g_z + (size_t)s3 * 256 + dbase));
        acc.x += fmaf(v0.x, o0, fmaf(v1.x, o1, fmaf(v2.x, o2, v3.x * o3)));
        acc.y += fmaf(v0.y, o0, fmaf(v1.y, o1, fmaf(v2.y, o2, v3.y * o3)));
        acc.z += fmaf(v0.z, o0, fmaf(v1.z, o1, fmaf(v2.z, o2, v3.z * o3)));
        acc.w += fmaf(v0.w, o0, fmaf(v1.w, o1, fmaf(v2.w, o2, v3.w * o3)));
    }
    for (; p < end; ++p) {
        const int s = __ldg(&g_cols[p]);
        const float o = __ldg(&g_isout[s]);
        const float4 v = __ldg((const float4*)(g_z + (size_t)s * 256 + dbase));
        acc.x = fmaf(v.x, o, acc.x); acc.y = fmaf(v.y, o, acc.y);
        acc.z = fmaf(v.z, o, acc.z); acc.w = fmaf(v.w, o, acc.w);
    }

    const float isn = g_isin[n];
    const float osc = g_isout[n];
    const float4 b4 = *(const float4*)(bias + dbase);
    float4 r;
    r.x = fmaxf(fmaf(acc.x, isn, b4.x), 0.f) * osc;
    r.y = fmaxf(fmaf(acc.y, isn, b4.y), 0.f) * osc;
    r.z = fmaxf(fmaf(acc.z, isn, b4.z), 0.f) * osc;
    r.w = fmaxf(fmaf(acc.w, isn, b4.w), 0.f) * osc;
    *(float4*)(g_h + (size_t)n * 256 + dbase) = r;
}

// ---------------- layer-2 SpMM: plain gather, 8-edge unroll ----------------
__global__ __launch_bounds__(256)
void spmm_warp8_kernel(const float* __restrict__ bias, int half)
{
    const int warp = threadIdx.x >> 5;
    const int lane = threadIdx.x & 31;
    const int n = blockIdx.x * 8 + warp;
    if (n >= NN) return;
    const int dbase = half * 128 + lane * 4;

    const int beg = g_rowptr[n];
    const int end = g_rowptr[n + 1];

    float4 acc = make_float4(0.f, 0.f, 0.f, 0.f);
    int p = beg;
    for (; p + 8 <= end; p += 8) {
        int s[8];
        #pragma unroll
        for (int q = 0; q < 8; q++) s[q] = __ldg(&g_cols[p + q]);
        float4 v[8];
        #pragma unroll
        for (int q = 0; q < 8; q++)
            v[q] = __ldg((const float4*)(g_z + (size_t)s[q] * 256 + dbase));
        acc.x += ((v[0].x + v[1].x) + (v[2].x + v[3].x)) + ((v[4].x + v[5].x) + (v[6].x + v[7].x));
        acc.y += ((v[0].y + v[1].y) + (v[2].y + v[3].y)) + ((v[4].y + v[5].y) + (v[6].y + v[7].y));
        acc.z += ((v[0].z + v[1].z) + (v[2].z + v[3].z)) + ((v[4].z + v[5].z) + (v[6].z + v[7].z));
        acc.w += ((v[0].w + v[1].w) + (v[2].w + v[3].w)) + ((v[4].w + v[5].w) + (v[6].w + v[7].w));
    }
    for (; p + 4 <= end; p += 4) {
        const int s0 = __ldg(&g_cols[p + 0]);
        const int s1 = __ldg(&g_cols[p + 1]);
        const int s2 = __ldg(&g_cols[p + 2]);
        const int s3 = __ldg(&g_cols[p + 3]);
        const float4 v0 = __ldg((const float4*)(g_z + (size_t)s0 * 256 + dbase));
        const float4 v1 = __ldg((const float4*)(g_z + (size_t)s1 * 256 + dbase));
        const float4 v2 = __ldg((const float4*)(g_z + (size_t)s2 * 256 + dbase));
        const float4 v3 = __ldg((const float4*)(g_z + (size_t)s3 * 256 + dbase));
        acc.x += (v0.x + v1.x) + (v2.x + v3.x);
        acc.y += (v0.y + v1.y) + (v2.y + v3.y);
        acc.z += (v0.z + v1.z) + (v2.z + v3.z);
        acc.w += (v0.w + v1.w) + (v2.w + v3.w);
    }
    for (; p < end; ++p) {
        const int s = __ldg(&g_cols[p]);
        const float4 v = __ldg((const float4*)(g_z + (size_t)s * 256 + dbase));
        acc.x += v.x; acc.y += v.y; acc.z += v.z; acc.w += v.w;
    }

    const float isn = g_isin[n];
    const float osc = g_isout[n];
    const float4 b4 = *(const float4*)(bias + dbase);
    float4 r;
    r.x = fmaxf(fmaf(acc.x, isn, b4.x), 0.f) * osc;
    r.y = fmaxf(fmaf(acc.y, isn, b4.y), 0.f) * osc;
    r.z = fmaxf(fmaf(acc.z, isn, b4.z), 0.f) * osc;
    r.w = fmaxf(fmaf(acc.w, isn, b4.w), 0.f) * osc;
    *(float4*)(g_h + (size_t)n * 256 + dbase) = r;
}

// ---------------- layer-3 SpMM (D=40) + log_softmax, warp-per-node ----------------
__global__ __launch_bounds__(256)
void spmm_logsoftmax_kernel(const float* __restrict__ bias, float* __restrict__ out)
{
    const int warp = threadIdx.x >> 5;
    const int lane = threadIdx.x & 31;
    const int n = blockIdx.x * 8 + warp;
    if (n >= NN) return;
    const bool act = (lane < DOUT / 2);
    const int d0 = lane * 2;

    const int beg = g_rowptr[n];
    const int end = g_rowptr[n + 1];

    float2 acc = make_float2(0.f, 0.f);
    int p = beg;
    for (; p + 4 <= end; p += 4) {
        int s[4];
        #pragma unroll
        for (int q = 0; q < 4; q++) s[q] = __ldg(&g_cols[p + q]);
        if (act) {
            #pragma unroll
            for (int q = 0; q < 4; q++) {
                const float2 v = __ldg((const float2*)(g_z + (size_t)s[q] * DOUT + d0));
                acc.x += v.x; acc.y += v.y;
            }
        }
    }
    for (; p < end; ++p) {
        const int s = __ldg(&g_cols[p]);
        if (act) {
            const float2 v = __ldg((const float2*)(g_z + (size_t)s * DOUT + d0));
            acc.x += v.x; acc.y += v.y;
        }
    }

    const float isn = g_isin[n];
    float v0 = -INFINITY, v1 = -INFINITY;
    if (act) {
        v0 = fmaf(acc.x, isn, __ldg(&bias[d0]));
        v1 = fmaf(acc.y, isn, __ldg(&bias[d0 + 1]));
    }

    float mx = fmaxf(v0, v1);
    #pragma unroll
    for (int off = 16; off > 0; off >>= 1)
        mx = fmaxf(mx, __shfl_xor_sync(0xffffffffu, mx, off));

    float e = act ? (expf(v0 - mx) + expf(v1 - mx)) : 0.f;
    #pragma unroll
    for (int off = 16; off > 0; off >>= 1)
        e += __shfl_xor_sync(0xffffffffu, e, off);

    const float lse = mx + logf(e);
    if (act) {
        float2 r = make_float2(v0 - lse, v1 - lse);
        *(float2*)(out + (size_t)n * DOUT + d0) = r;
    }
}

// ---------------- launch ----------------
extern "C" void kernel_launch(void* const* d_in, const int* in_sizes, int n_in,
                              void* d_out, int out_size)
{
    const float* x  = (const float*)d_in[0];
    const float* W1 = (const float*)d_in[1];
    const float* b1 = (const float*)d_in[2];
    const float* W2 = (const float*)d_in[3];
    const float* b2 = (const float*)d_in[4];
    const float* W3 = (const float*)d_in[5];
    const float* b3 = (const float*)d_in[6];
    const int*  src = (const int*)d_in[7];
    const int*  dst = (const int*)d_in[8];
    float* out = (float*)d_out;

    // side stream + events (created once; resources, not work)
    static cudaStream_t s2 = nullptr;
    static cudaEvent_t ev_fork = nullptr, ev_join = nullptr;
    static cudaEvent_t evG1a = nullptr, evS1a = nullptr, evG2a = nullptr, evS2a = nullptr;
    if (s2 == nullptr) {
        cudaStreamCreateWithFlags(&s2, cudaStreamNonBlocking);
        cudaEventCreateWithFlags(&ev_fork, cudaEventDisableTiming);
        cudaEventCreateWithFlags(&ev_join, cudaEventDisableTiming);
        cudaEventCreateWithFlags(&evG1a, cudaEventDisableTiming);
        cudaEventCreateWithFlags(&evS1a, cudaEventDisableTiming);
        cudaEventCreateWithFlags(&evG2a, cudaEventDisableTiming);
        cudaEventCreateWithFlags(&evS2a, cudaEventDisableTiming);
    }

    const int nb_e = (EE + 255) / 256;
    const int gm = (NN + 127) / 128;
    const int gw = (NN + 7) / 8;

    // ---- fork: prep chain on s2 ----
    cudaEventRecord(ev_fork, 0);
    cudaStreamWaitEvent(s2, ev_fork, 0);
    degree_kernel<<<nb_e, 256, 0, s2>>>(src, dst);
    scan_partial_kernel<<<NB_SCAN, 1024, 0, s2>>>();
    scan_mid_kernel<<<1, 32, 0, s2>>>();
    scan_final_kernel<<<NB_SCAN, 1024, 0, s2>>>();
    csr_fill_kernel<<<nb_e, 256, 0, s2>>>(src, dst);
    cudaEventRecord(ev_join, s2);

    // ---- layer 1 ----
    gemm_kernel<<<gm, 256>>>(x, 1, W1, NN, 256, 0);        // z1 cols 0..127
    cudaEventRecord(evG1a, 0);
    gemm_kernel<<<gm, 256>>>(x, 1, W1, NN, 256, 1);        // z1 cols 128..255

    // SpMM1 half0 on s2: needs graph (s2-ordered) + z1 col-block0; overlaps GEMM1b tail
    cudaStreamWaitEvent(s2, evG1a, 0);
    spmm_warp_kernel<<<gw, 256, 0, s2>>>(b1, 0);
    cudaEventRecord(evS1a, s2);

    // SpMM1 half1 on main: after GEMM1b (stream order) + graph
    cudaStreamWaitEvent(0, ev_join, 0);
    spmm_warp_kernel<<<gw, 256>>>(b1, 1);

    // ---- layer 2 ----
    cudaStreamWaitEvent(0, evS1a, 0);                       // GEMM2 needs full h1
    gemm_kernel<<<gm, 256>>>(x, 0, W2, NN, 256, 0);
    cudaEventRecord(evG2a, 0);
    gemm_kernel<<<gm, 256>>>(x, 0, W2, NN, 256, 1);

    cudaStreamWaitEvent(s2, evG2a, 0);
    spmm_warp8_kernel<<<gw, 256, 0, s2>>>(b2, 0);
    cudaEventRecord(evS2a, s2);

    spmm_warp8_kernel<<<gw, 256>>>(b2, 1);

    // ---- layer 3 ----
    cudaStreamWaitEvent(0, evS2a, 0);                       // gemm40 needs full h2
    gemm40_kernel<<<gm, 128>>>(W3, NN);
    spmm_logsoftmax_kernel<<<gw, 256>>>(b3, out);
}